// round 6
// baseline (speedup 1.0000x reference)
#include <cuda_runtime.h>
#include <cuda_bf16.h>
#include <cstdint>
#include <math.h>

// ---------------------------------------------------------------------------
#define PIX33 1089
#define PITCH33 1092
#define PIX65 4225
#define PIX129 16641
#define CIN 128
#define COUT 768
#define NB 8
#define NCH 19
#define NSLICE 4

typedef unsigned long long u64;

__device__ __forceinline__ u64 pack2(float lo, float hi) {
    u64 r; asm("mov.b64 %0, {%1, %2};" : "=l"(r) : "f"(lo), "f"(hi)); return r;
}
__device__ __forceinline__ void unpack2(float& lo, float& hi, u64 v) {
    asm("mov.b64 {%0, %1}, %2;" : "=f"(lo), "=f"(hi) : "l"(v));
}
__device__ __forceinline__ void fma2(u64& d, u64 a, u64 b) {
    asm("fma.rn.f32x2 %0, %1, %2, %3;" : "=l"(d) : "l"(a), "l"(b), "l"(d));
}

__device__ __align__(16) float g_Wt[CIN * COUT];
__device__ __align__(16) float g_y33[NB * COUT * PITCH33];
__device__ __align__(16) float g_Ut[NB * NCH * PIX129];
__device__ __align__(16) float g_Us[NB * NCH * PIX129];
__device__ __align__(16) float g_part[NSLICE][NB][4][PIX65];
__device__ double g_pi;
__device__ double g_d[2][NB * NCH];
__device__ double g_Wz[2][NB * NCH];
__device__ double g_R[2][NB][190];

// ---------------------------------------------------------------------------
__global__ void zero_kernel() {
    int t = blockIdx.x * blockDim.x + threadIdx.x;
    if (t == 0) g_pi = 0.0;
    if (t < NB * NCH) {
        g_d[0][t] = 0.0; g_d[1][t] = 0.0;
        g_Wz[0][t] = 0.0; g_Wz[1][t] = 0.0;
    }
    if (t < 2 * NB * 190) ((double*)g_R)[t] = 0.0;
}

__global__ void transpose_w_kernel(const float* __restrict__ conv_w) {
    int idx = blockIdx.x * blockDim.x + threadIdx.x;
    if (idx < CIN * COUT) {
        int c = idx / COUT, o = idx - c * COUT;
        g_Wt[idx] = conv_w[o * CIN + c];
    }
}

// ---------------------------------------------------------------------------
// GEMM with packed f32x2 FMA: 128x128 tile, 8x8 per thread (as 8x4 f32x2).
// ---------------------------------------------------------------------------
__global__ __launch_bounds__(256) void gemm_kernel(const float* __restrict__ s_out,
                                                   const float* __restrict__ bias) {
    int b    = blockIdx.z;
    int pix0 = blockIdx.x * 128;
    int o0   = blockIdx.y * 128;

    __shared__ __align__(16) float As[16][128];
    __shared__ __align__(16) float Bs[16][128];

    int tid = threadIdx.x;
    int tx = tid & 15, ty = tid >> 4;

    u64 acc2[8][4];
#pragma unroll
    for (int i = 0; i < 8; i++)
#pragma unroll
        for (int j = 0; j < 4; j++) acc2[i][j] = pack2(0.f, 0.f);

    const float* Ab = s_out + (size_t)b * CIN * PIX33;
    int kk = tid >> 4;
    int m0 = (tid & 15) * 8;

    for (int k0 = 0; k0 < CIN; k0 += 16) {
        const float* arow = Ab + (size_t)(k0 + kk) * PIX33;
#pragma unroll
        for (int u = 0; u < 8; u++) {
            int pix = pix0 + m0 + u;
            As[kk][m0 + u] = (pix < PIX33) ? arow[pix] : 0.f;
        }
        const float* brow = g_Wt + (size_t)(k0 + kk) * COUT + o0 + m0;
        *(float4*)&Bs[kk][m0]     = *(const float4*)brow;
        *(float4*)&Bs[kk][m0 + 4] = *(const float4*)(brow + 4);
        __syncthreads();

#pragma unroll
        for (int k2 = 0; k2 < 16; k2++) {
            float4 a0 = *(const float4*)&As[k2][tx * 4];
            float4 a1 = *(const float4*)&As[k2][64 + tx * 4];
            float4 b0 = *(const float4*)&Bs[k2][ty * 4];
            float4 b1 = *(const float4*)&Bs[k2][64 + ty * 4];
            u64 bp[4];
            bp[0] = pack2(b0.x, b0.y);
            bp[1] = pack2(b0.z, b0.w);
            bp[2] = pack2(b1.x, b1.y);
            bp[3] = pack2(b1.z, b1.w);
            float av[8] = {a0.x, a0.y, a0.z, a0.w, a1.x, a1.y, a1.z, a1.w};
#pragma unroll
            for (int i = 0; i < 8; i++) {
                u64 ad = pack2(av[i], av[i]);
#pragma unroll
                for (int j = 0; j < 4; j++) fma2(acc2[i][j], ad, bp[j]);
            }
        }
        __syncthreads();
    }

    // Epilogue: each jp covers two consecutive o columns.
#pragma unroll
    for (int jp = 0; jp < 4; jp++) {
        int colbase = (jp < 2) ? (ty * 4 + jp * 2) : (64 + ty * 4 + (jp - 2) * 2);
        int o = o0 + colbase;
        float bb0 = bias[o], bb1 = bias[o + 1];
        float va[8], vb[8];
#pragma unroll
        for (int i = 0; i < 8; i++) unpack2(va[i], vb[i], acc2[i][jp]);
        float* orow0 = g_y33 + ((size_t)b * COUT + o) * PITCH33;
        float* orow1 = orow0 + PITCH33;
#pragma unroll
        for (int g = 0; g < 2; g++) {
            int p = pix0 + g * 64 + tx * 4;
            float x0 = va[g*4+0] + bb0, x1 = va[g*4+1] + bb0;
            float x2 = va[g*4+2] + bb0, x3 = va[g*4+3] + bb0;
            float y0 = vb[g*4+0] + bb1, y1 = vb[g*4+1] + bb1;
            float y2 = vb[g*4+2] + bb1, y3 = vb[g*4+3] + bb1;
            if (p + 3 < PIX33) {
                *(float4*)&orow0[p] = make_float4(x0, x1, x2, x3);
                *(float4*)&orow1[p] = make_float4(y0, y1, y2, y3);
            } else {
                if (p + 0 < PIX33) { orow0[p + 0] = x0; orow1[p + 0] = y0; }
                if (p + 1 < PIX33) { orow0[p + 1] = x1; orow1[p + 1] = y1; }
                if (p + 2 < PIX33) { orow0[p + 2] = x2; orow1[p + 2] = y2; }
                if (p + 3 < PIX33) { orow0[p + 3] = x3; orow1[p + 3] = y3; }
            }
        }
    }
}

// ---------------------------------------------------------------------------
// pi partial: 32 pixels x 192 channels per block.
// ---------------------------------------------------------------------------
__global__ __launch_bounds__(256, 7) void pi_partial_kernel(const float* __restrict__ t_out) {
    int b     = blockIdx.y;
    int slice = blockIdx.z;
    int tx = threadIdx.x, ty = threadIdx.y;
    int p  = blockIdx.x * 32 + tx;
    bool valid = (p < PIX65);
    int pp = valid ? p : 0;

    int y = pp / 65, x = pp - y * 65;
    int y0 = y >> 1, x0 = x >> 1;
    int y1 = min(y0 + 1, 32), x1 = min(x0 + 1, 32);
    float wy = (y & 1) * 0.5f, wx = (x & 1) * 0.5f;
    float w00 = (1.f - wy) * (1.f - wx);
    float w01 = (1.f - wy) * wx;
    float w10 = wy * (1.f - wx);
    float w11 = wy * wx;
    int i00 = y0 * 33 + x0, i01 = y0 * 33 + x1;
    int i10 = y1 * 33 + x0, i11 = y1 * 33 + x1;
    bool nx = (wx > 0.f), ny = (wy > 0.f);

    const float* tp = t_out + (size_t)b * COUT * PIX65
                    + (size_t)(slice * 192 + ty) * PIX65 + pp;
    const float* yp = g_y33 + ((size_t)b * COUT + slice * 192 + ty) * PITCH33;

    float S1 = 0.f, S2 = 0.f, S3 = 0.f, Ss = 0.f;
    if (valid) {
        for (int k = 0; k < 6; k++) {
#pragma unroll
            for (int u = 0; u < 4; u++) {
                const float* tq = tp + (size_t)(u * 8) * PIX65;
                const float* Y  = yp + (size_t)(u * 8) * PITCH33;
                float zt = *tq;
                float zs = w00 * Y[i00];
                if (nx) zs += w01 * Y[i01];
                if (ny) {
                    zs += w10 * Y[i10];
                    if (nx) zs += w11 * Y[i11];
                }
                float e = __expf(zt);
                S1 += e;
                S2 += zt * e;
                S3 += zs * e;
                Ss += __expf(zs);
            }
            tp += (size_t)32 * PIX65;
            yp += (size_t)32 * PITCH33;
        }
    }

    __shared__ float r1[8][32], r2[8][32], r3[8][32], rs[8][32];
    r1[ty][tx] = S1; r2[ty][tx] = S2; r3[ty][tx] = S3; rs[ty][tx] = Ss;
    __syncthreads();

    if (ty == 0 && valid) {
#pragma unroll
        for (int u = 1; u < 8; u++) {
            S1 += r1[u][tx]; S2 += r2[u][tx];
            S3 += r3[u][tx]; Ss += rs[u][tx];
        }
        g_part[slice][b][0][p] = S1;
        g_part[slice][b][1][p] = S2;
        g_part[slice][b][2][p] = S3;
        g_part[slice][b][3][p] = Ss;
    }
}

__global__ void pi_final_kernel() {
    int b = blockIdx.y;
    int p = blockIdx.x * 256 + threadIdx.x;
    float v = 0.f;
    if (p < PIX65) {
        float S1 = 0.f, S2 = 0.f, S3 = 0.f, Ss = 0.f;
#pragma unroll
        for (int s = 0; s < NSLICE; s++) {
            S1 += g_part[s][b][0][p];
            S2 += g_part[s][b][1][p];
            S3 += g_part[s][b][2][p];
            Ss += g_part[s][b][3][p];
        }
        float inv = 1.f / S1;
        v = S2 * inv - logf(S1) - S3 * inv + logf(Ss);
    }
    __shared__ float red[256];
    int tid = threadIdx.x;
    red[tid] = v;
    __syncthreads();
    for (int o = 128; o; o >>= 1) {
        if (tid < o) red[tid] += red[tid + o];
        __syncthreads();
    }
    if (tid == 0) atomicAdd(&g_pi, (double)red[0]);
}

// ---------------------------------------------------------------------------
__device__ __forceinline__ void prep_reduce_store(float dloc, float wloc,
                                                  int side, int row) {
    __shared__ float rd[256], rw[256];
    int tid = threadIdx.x;
    rd[tid] = dloc; rw[tid] = wloc;
    __syncthreads();
    for (int o = 128; o; o >>= 1) {
        if (tid < o) { rd[tid] += rd[tid + o]; rw[tid] += rw[tid + o]; }
        __syncthreads();
    }
    if (tid == 0) {
        atomicAdd(&g_d[side][row], (double)rd[0]);
        atomicAdd(&g_Wz[side][row], (double)rw[0]);
    }
}

__global__ void tprep_kernel(const float* __restrict__ t_logit) {
    int row = blockIdx.y;
    int k = blockIdx.x * 256 + threadIdx.x;
    float dloc = 0.f, wloc = 0.f;
    if (k < PIX129) {
        int y = k / 129, x = k - y * 129;
        int y0 = y >> 1, x0 = x >> 1;
        int y1 = min(y0 + 1, 64), x1 = min(x0 + 1, 64);
        float wy = (y & 1) * 0.5f, wx = (x & 1) * 0.5f;
        const float* src = t_logit + (size_t)row * PIX65;
        float top = (1.f - wx) * src[y0 * 65 + x0] + wx * src[y0 * 65 + x1];
        float bot = (1.f - wx) * src[y1 * 65 + x0] + wx * src[y1 * 65 + x1];
        float z = (1.f - wy) * top + wy * bot;
        float u = __expf(z);
        g_Ut[(size_t)row * PIX129 + k] = u;
        dloc = u; wloc = u * z;
    }
    prep_reduce_store(dloc, wloc, 1, row);
}

__global__ void sprep_kernel(const float* __restrict__ s_logit) {
    int row = blockIdx.y;
    int k = blockIdx.x * 256 + threadIdx.x;
    float dloc = 0.f, wloc = 0.f;
    if (k < PIX129) {
        float z = s_logit[(size_t)row * PIX129 + k];
        float u = __expf(z);
        g_Us[(size_t)row * PIX129 + k] = u;
        dloc = u; wloc = u * z;
    }
    prep_reduce_store(dloc, wloc, 0, row);
}

// ---------------------------------------------------------------------------
// Gram via packed f32x2: rows padded to 514 floats (8B-aligned u64 rows).
// ---------------------------------------------------------------------------
__global__ void gram_kernel() {
    int side = blockIdx.z;
    int b    = blockIdx.y;
    int k0   = blockIdx.x * 512;
    const float* U = (side ? g_Ut : g_Us) + (size_t)b * NCH * PIX129;

    __shared__ __align__(8) float sm[NCH][514];
    int tid = threadIdx.x;
    for (int idx = tid; idx < NCH * 512; idx += 256) {
        int i = idx >> 9, kk = idx & 511;
        int k = k0 + kk;
        sm[i][kk] = (k < PIX129) ? U[(size_t)i * PIX129 + k] : 0.f;
    }
    __syncthreads();

    if (tid < 190) {
        int i = 0, t = tid;
        while (t >= NCH - i) { t -= NCH - i; i++; }
        int j = i + t;
        const u64* ri = (const u64*)&sm[i][0];
        const u64* rj = (const u64*)&sm[j][0];
        u64 acc2 = pack2(0.f, 0.f);
#pragma unroll 4
        for (int kk = 0; kk < 256; kk++) fma2(acc2, ri[kk], rj[kk]);
        float lo, hi;
        unpack2(lo, hi, acc2);
        atomicAdd(&g_R[side][b][tid], (double)(lo + hi));
    }
}

// ---------------------------------------------------------------------------
__global__ void finalize_kernel(float* __restrict__ out) {
    int tid = threadIdx.x;
    __shared__ double sE[2][NCH];
    __shared__ double sG[2][361];
    __shared__ double sS[2][361];
    __shared__ double sN[2][NCH];
    __shared__ double red[512];

    if (tid < 2 * NCH) {
        int side = tid / NCH, i = tid % NCH;
        double e = 0.0;
        for (int b = 0; b < NB; b++) {
            double d = g_d[side][b * NCH + i];
            e += g_Wz[side][b * NCH + i] / d - log(d);
        }
        sE[side][i] = e;
    }
    if (tid < 361) {
        int i = tid / NCH, j = tid % NCH;
        int mi = min(i, j), mj = max(i, j);
        int p = mi * NCH - mi * (mi - 1) / 2 + (mj - mi);
        for (int side = 0; side < 2; side++) {
            double g = 0.0;
            for (int b = 0; b < NB; b++)
                g += g_R[side][b][p] /
                     (g_d[side][b * NCH + i] * g_d[side][b * NCH + j]);
            sG[side][tid] = g;
        }
    }
    __syncthreads();
    if (tid < 361) {
        int i = tid / NCH, j = tid % NCH;
        int mx = max(i, j);
        sS[0][tid] = (sE[0][mx] - sG[0][tid]) / (double)NB;
        sS[1][tid] = (sE[1][mx] - sG[1][tid]) / (double)NB;
    }
    __syncthreads();
    if (tid < 2 * NCH) {
        int side = tid / NCH, i = tid % NCH;
        double s = 0.0;
        for (int j = 0; j < NCH; j++) {
            double v = sS[side][i * NCH + j];
            s += v * v;
        }
        double n = sqrt(s);
        sN[side][i] = (n > 1e-12) ? n : 1e-12;
    }
    __syncthreads();
    double v = 0.0;
    if (tid < 361) {
        int i = tid / NCH;
        double dd = sS[0][tid] / sN[0][i] - sS[1][tid] / sN[1][i];
        v = dd * dd;
    }
    red[tid] = v;
    __syncthreads();
    for (int o = 256; o; o >>= 1) {
        if (tid < o) red[tid] += red[tid + o];
        __syncthreads();
    }
    if (tid == 0) {
        out[0] = (float)(g_pi / 25958400.0);
        out[1] = (float)red[0];
    }
}

// ---------------------------------------------------------------------------
extern "C" void kernel_launch(void* const* d_in, const int* in_sizes, int n_in,
                              void* d_out, int out_size) {
    const float *ptr[6] = {nullptr, nullptr, nullptr, nullptr, nullptr, nullptr};
    const int want[6] = {1115136, 25958400, 642200, 2529912, 98304, 768};

    for (int i = 0; i < n_in; i++) {
        long long s = in_sizes[i];
        for (int k = 0; k < 6; k++) {
            if (s == (long long)want[k] || s == 4LL * want[k]) {
                if (!ptr[k]) ptr[k] = (const float*)d_in[i];
            }
        }
    }
    if (n_in >= 6) {
        for (int k = 0; k < 6; k++)
            if (!ptr[k]) ptr[k] = (const float*)d_in[k];
    }

    const float* s_out   = ptr[0];
    const float* t_out   = ptr[1];
    const float* t_logit = ptr[2];
    const float* s_logit = ptr[3];
    const float* conv_w  = ptr[4];
    const float* conv_b  = ptr[5];

    zero_kernel<<<15, 256>>>();
    transpose_w_kernel<<<(CIN * COUT + 255) / 256, 256>>>(conv_w);
    gemm_kernel<<<dim3(9, 6, NB), 256>>>(s_out, conv_b);
    pi_partial_kernel<<<dim3((PIX65 + 31) / 32, NB, NSLICE), dim3(32, 8)>>>(t_out);
    pi_final_kernel<<<dim3((PIX65 + 255) / 256, NB), 256>>>();
    tprep_kernel<<<dim3((PIX129 + 255) / 256, NB * NCH), 256>>>(t_logit);
    sprep_kernel<<<dim3((PIX129 + 255) / 256, NB * NCH), 256>>>(s_logit);
    gram_kernel<<<dim3((PIX129 + 511) / 512, NB, 2), 256>>>();
    finalize_kernel<<<1, 512>>>((float*)d_out);
}

// round 7
// speedup vs baseline: 1.2813x; 1.2813x over previous
#include <cuda_runtime.h>
#include <cuda_bf16.h>
#include <cstdint>
#include <math.h>

// ---------------------------------------------------------------------------
#define PIX33 1089
#define PITCH33 1092
#define PIX65 4225
#define PIX129 16641
#define CIN 128
#define COUT 768
#define NB 8
#define NCH 19
#define NSLICE 4

typedef unsigned long long u64;

__device__ __forceinline__ u64 pack2(float lo, float hi) {
    u64 r; asm("mov.b64 %0, {%1, %2};" : "=l"(r) : "f"(lo), "f"(hi)); return r;
}
__device__ __forceinline__ void unpack2(float& lo, float& hi, u64 v) {
    asm("mov.b64 {%0, %1}, %2;" : "=f"(lo), "=f"(hi) : "l"(v));
}
__device__ __forceinline__ void fma2(u64& d, u64 a, u64 b) {
    asm("fma.rn.f32x2 %0, %1, %2, %3;" : "=l"(d) : "l"(a), "l"(b), "l"(d));
}

__device__ __align__(16) float g_Wt[CIN * COUT];
__device__ __align__(16) float g_y33[NB * COUT * PITCH33];
__device__ __align__(16) float g_Ut[NB * NCH * PIX129];
__device__ __align__(16) float g_Us[NB * NCH * PIX129];
__device__ __align__(16) float g_part[NSLICE][NB][4][PIX65];
__device__ double g_pi;
__device__ double g_d[2][NB * NCH];
__device__ double g_Wz[2][NB * NCH];
__device__ double g_R[2][NB][190];

// Side stream + fork/join events, created once at program init (before any
// harness memory checkpoint). No device-memory APIs involved.
static cudaStream_t g_s2;
static cudaEvent_t g_e1, g_e2;
namespace {
struct StreamInit {
    StreamInit() {
        cudaStreamCreateWithFlags(&g_s2, cudaStreamNonBlocking);
        cudaEventCreateWithFlags(&g_e1, cudaEventDisableTiming);
        cudaEventCreateWithFlags(&g_e2, cudaEventDisableTiming);
    }
};
static StreamInit g_si;
}

// ---------------------------------------------------------------------------
__global__ void zero_kernel() {
    int t = blockIdx.x * blockDim.x + threadIdx.x;
    if (t == 0) g_pi = 0.0;
    if (t < NB * NCH) {
        g_d[0][t] = 0.0; g_d[1][t] = 0.0;
        g_Wz[0][t] = 0.0; g_Wz[1][t] = 0.0;
    }
    if (t < 2 * NB * 190) ((double*)g_R)[t] = 0.0;
}

__global__ void transpose_w_kernel(const float* __restrict__ conv_w) {
    int idx = blockIdx.x * blockDim.x + threadIdx.x;
    if (idx < CIN * COUT) {
        int c = idx / COUT, o = idx - c * COUT;
        g_Wt[idx] = conv_w[o * CIN + c];
    }
}

// ---------------------------------------------------------------------------
// GEMM with packed f32x2 FMA: 128x128 tile, 8x8 per thread (as 8x4 f32x2).
// ---------------------------------------------------------------------------
__global__ __launch_bounds__(256) void gemm_kernel(const float* __restrict__ s_out,
                                                   const float* __restrict__ bias) {
    int b    = blockIdx.z;
    int pix0 = blockIdx.x * 128;
    int o0   = blockIdx.y * 128;

    __shared__ __align__(16) float As[16][128];
    __shared__ __align__(16) float Bs[16][128];

    int tid = threadIdx.x;
    int tx = tid & 15, ty = tid >> 4;

    u64 acc2[8][4];
#pragma unroll
    for (int i = 0; i < 8; i++)
#pragma unroll
        for (int j = 0; j < 4; j++) acc2[i][j] = pack2(0.f, 0.f);

    const float* Ab = s_out + (size_t)b * CIN * PIX33;
    int kk = tid >> 4;
    int m0 = (tid & 15) * 8;

    for (int k0 = 0; k0 < CIN; k0 += 16) {
        const float* arow = Ab + (size_t)(k0 + kk) * PIX33;
#pragma unroll
        for (int u = 0; u < 8; u++) {
            int pix = pix0 + m0 + u;
            As[kk][m0 + u] = (pix < PIX33) ? arow[pix] : 0.f;
        }
        const float* brow = g_Wt + (size_t)(k0 + kk) * COUT + o0 + m0;
        *(float4*)&Bs[kk][m0]     = *(const float4*)brow;
        *(float4*)&Bs[kk][m0 + 4] = *(const float4*)(brow + 4);
        __syncthreads();

#pragma unroll
        for (int k2 = 0; k2 < 16; k2++) {
            float4 a0 = *(const float4*)&As[k2][tx * 4];
            float4 a1 = *(const float4*)&As[k2][64 + tx * 4];
            float4 b0 = *(const float4*)&Bs[k2][ty * 4];
            float4 b1 = *(const float4*)&Bs[k2][64 + ty * 4];
            u64 bp[4];
            bp[0] = pack2(b0.x, b0.y);
            bp[1] = pack2(b0.z, b0.w);
            bp[2] = pack2(b1.x, b1.y);
            bp[3] = pack2(b1.z, b1.w);
            float av[8] = {a0.x, a0.y, a0.z, a0.w, a1.x, a1.y, a1.z, a1.w};
#pragma unroll
            for (int i = 0; i < 8; i++) {
                u64 ad = pack2(av[i], av[i]);
#pragma unroll
                for (int j = 0; j < 4; j++) fma2(acc2[i][j], ad, bp[j]);
            }
        }
        __syncthreads();
    }

#pragma unroll
    for (int jp = 0; jp < 4; jp++) {
        int colbase = (jp < 2) ? (ty * 4 + jp * 2) : (64 + ty * 4 + (jp - 2) * 2);
        int o = o0 + colbase;
        float bb0 = bias[o], bb1 = bias[o + 1];
        float va[8], vb[8];
#pragma unroll
        for (int i = 0; i < 8; i++) unpack2(va[i], vb[i], acc2[i][jp]);
        float* orow0 = g_y33 + ((size_t)b * COUT + o) * PITCH33;
        float* orow1 = orow0 + PITCH33;
#pragma unroll
        for (int g = 0; g < 2; g++) {
            int p = pix0 + g * 64 + tx * 4;
            float x0 = va[g*4+0] + bb0, x1 = va[g*4+1] + bb0;
            float x2 = va[g*4+2] + bb0, x3 = va[g*4+3] + bb0;
            float y0 = vb[g*4+0] + bb1, y1 = vb[g*4+1] + bb1;
            float y2 = vb[g*4+2] + bb1, y3 = vb[g*4+3] + bb1;
            if (p + 3 < PIX33) {
                *(float4*)&orow0[p] = make_float4(x0, x1, x2, x3);
                *(float4*)&orow1[p] = make_float4(y0, y1, y2, y3);
            } else {
                if (p + 0 < PIX33) { orow0[p + 0] = x0; orow1[p + 0] = y0; }
                if (p + 1 < PIX33) { orow0[p + 1] = x1; orow1[p + 1] = y1; }
                if (p + 2 < PIX33) { orow0[p + 2] = x2; orow1[p + 2] = y2; }
                if (p + 3 < PIX33) { orow0[p + 3] = x3; orow1[p + 3] = y3; }
            }
        }
    }
}

// ---------------------------------------------------------------------------
// pi partial v3: 64 pixels x 192 channels per block; each thread owns TWO
// pixels (p, p+32) -> two independent load/exp chains (MLP x2).
// ---------------------------------------------------------------------------
__global__ __launch_bounds__(256) void pi_partial_kernel(const float* __restrict__ t_out) {
    int b     = blockIdx.y;
    int slice = blockIdx.z;
    int tx = threadIdx.x, ty = threadIdx.y;
    int pA = blockIdx.x * 64 + tx;
    int pB = pA + 32;
    bool vA = (pA < PIX65), vB = (pB < PIX65);
    int ppA = vA ? pA : 0;
    int ppB = vB ? pB : 0;

    // Bilinear constants, pixel A
    int yA = ppA / 65, xA = ppA - yA * 65;
    int y0A = yA >> 1, x0A = xA >> 1;
    int y1A = min(y0A + 1, 32), x1A = min(x0A + 1, 32);
    float wyA = (yA & 1) * 0.5f, wxA = (xA & 1) * 0.5f;
    float a00 = (1.f - wyA) * (1.f - wxA), a01 = (1.f - wyA) * wxA;
    float a10 = wyA * (1.f - wxA),         a11 = wyA * wxA;
    int iA00 = y0A * 33 + x0A, iA01 = y0A * 33 + x1A;
    int iA10 = y1A * 33 + x0A, iA11 = y1A * 33 + x1A;

    // Bilinear constants, pixel B
    int yB = ppB / 65, xB = ppB - yB * 65;
    int y0B = yB >> 1, x0B = xB >> 1;
    int y1B = min(y0B + 1, 32), x1B = min(x0B + 1, 32);
    float wyB = (yB & 1) * 0.5f, wxB = (xB & 1) * 0.5f;
    float b00 = (1.f - wyB) * (1.f - wxB), b01 = (1.f - wyB) * wxB;
    float b10 = wyB * (1.f - wxB),         b11 = wyB * wxB;
    int iB00 = y0B * 33 + x0B, iB01 = y0B * 33 + x1B;
    int iB10 = y1B * 33 + x0B, iB11 = y1B * 33 + x1B;

    const float* tpA = t_out + (size_t)b * COUT * PIX65
                     + (size_t)(slice * 192 + ty) * PIX65 + ppA;
    const float* tpB = t_out + (size_t)b * COUT * PIX65
                     + (size_t)(slice * 192 + ty) * PIX65 + ppB;
    const float* yp  = g_y33 + ((size_t)b * COUT + slice * 192 + ty) * PITCH33;

    float S1a = 0.f, S2a = 0.f, S3a = 0.f, Ssa = 0.f;
    float S1b = 0.f, S2b = 0.f, S3b = 0.f, Ssb = 0.f;

    for (int k = 0; k < 6; k++) {
#pragma unroll
        for (int u = 0; u < 4; u++) {
            const float* Y  = yp + (size_t)(u * 8) * PITCH33;
            float ztA = tpA[(size_t)(u * 8) * PIX65];
            float ztB = tpB[(size_t)(u * 8) * PIX65];
            float zsA = a00 * Y[iA00] + a01 * Y[iA01]
                      + a10 * Y[iA10] + a11 * Y[iA11];
            float zsB = b00 * Y[iB00] + b01 * Y[iB01]
                      + b10 * Y[iB10] + b11 * Y[iB11];
            float eA = __expf(ztA);
            float eB = __expf(ztB);
            S1a += eA;        S1b += eB;
            S2a += ztA * eA;  S2b += ztB * eB;
            S3a += zsA * eA;  S3b += zsB * eB;
            Ssa += __expf(zsA);
            Ssb += __expf(zsB);
        }
        tpA += (size_t)32 * PIX65;
        tpB += (size_t)32 * PIX65;
        yp  += (size_t)32 * PITCH33;
    }

    __shared__ float r1[8][64], r2[8][64], r3[8][64], rs[8][64];
    r1[ty][tx] = S1a; r1[ty][tx + 32] = S1b;
    r2[ty][tx] = S2a; r2[ty][tx + 32] = S2b;
    r3[ty][tx] = S3a; r3[ty][tx + 32] = S3b;
    rs[ty][tx] = Ssa; rs[ty][tx + 32] = Ssb;
    __syncthreads();

    if (ty < 2) {
        int col = ty * 32 + tx;            // ty==0 -> pixel A, ty==1 -> pixel B
        int p   = blockIdx.x * 64 + col;
        if (p < PIX65) {
            float S1 = 0.f, S2 = 0.f, S3 = 0.f, Ss = 0.f;
#pragma unroll
            for (int u = 0; u < 8; u++) {
                S1 += r1[u][col]; S2 += r2[u][col];
                S3 += r3[u][col]; Ss += rs[u][col];
            }
            g_part[slice][b][0][p] = S1;
            g_part[slice][b][1][p] = S2;
            g_part[slice][b][2][p] = S3;
            g_part[slice][b][3][p] = Ss;
        }
    }
}

__global__ void pi_final_kernel() {
    int b = blockIdx.y;
    int p = blockIdx.x * 256 + threadIdx.x;
    float v = 0.f;
    if (p < PIX65) {
        float S1 = 0.f, S2 = 0.f, S3 = 0.f, Ss = 0.f;
#pragma unroll
        for (int s = 0; s < NSLICE; s++) {
            S1 += g_part[s][b][0][p];
            S2 += g_part[s][b][1][p];
            S3 += g_part[s][b][2][p];
            Ss += g_part[s][b][3][p];
        }
        float inv = 1.f / S1;
        v = S2 * inv - logf(S1) - S3 * inv + logf(Ss);
    }
    __shared__ float red[256];
    int tid = threadIdx.x;
    red[tid] = v;
    __syncthreads();
    for (int o = 128; o; o >>= 1) {
        if (tid < o) red[tid] += red[tid + o];
        __syncthreads();
    }
    if (tid == 0) atomicAdd(&g_pi, (double)red[0]);
}

// ---------------------------------------------------------------------------
__device__ __forceinline__ void prep_reduce_store(float dloc, float wloc,
                                                  int side, int row) {
    __shared__ float rd[256], rw[256];
    int tid = threadIdx.x;
    rd[tid] = dloc; rw[tid] = wloc;
    __syncthreads();
    for (int o = 128; o; o >>= 1) {
        if (tid < o) { rd[tid] += rd[tid + o]; rw[tid] += rw[tid + o]; }
        __syncthreads();
    }
    if (tid == 0) {
        atomicAdd(&g_d[side][row], (double)rd[0]);
        atomicAdd(&g_Wz[side][row], (double)rw[0]);
    }
}

__global__ void tprep_kernel(const float* __restrict__ t_logit) {
    int row = blockIdx.y;
    int k = blockIdx.x * 256 + threadIdx.x;
    float dloc = 0.f, wloc = 0.f;
    if (k < PIX129) {
        int y = k / 129, x = k - y * 129;
        int y0 = y >> 1, x0 = x >> 1;
        int y1 = min(y0 + 1, 64), x1 = min(x0 + 1, 64);
        float wy = (y & 1) * 0.5f, wx = (x & 1) * 0.5f;
        const float* src = t_logit + (size_t)row * PIX65;
        float top = (1.f - wx) * src[y0 * 65 + x0] + wx * src[y0 * 65 + x1];
        float bot = (1.f - wx) * src[y1 * 65 + x0] + wx * src[y1 * 65 + x1];
        float z = (1.f - wy) * top + wy * bot;
        float u = __expf(z);
        g_Ut[(size_t)row * PIX129 + k] = u;
        dloc = u; wloc = u * z;
    }
    prep_reduce_store(dloc, wloc, 1, row);
}

__global__ void sprep_kernel(const float* __restrict__ s_logit) {
    int row = blockIdx.y;
    int k = blockIdx.x * 256 + threadIdx.x;
    float dloc = 0.f, wloc = 0.f;
    if (k < PIX129) {
        float z = s_logit[(size_t)row * PIX129 + k];
        float u = __expf(z);
        g_Us[(size_t)row * PIX129 + k] = u;
        dloc = u; wloc = u * z;
    }
    prep_reduce_store(dloc, wloc, 0, row);
}

// ---------------------------------------------------------------------------
__global__ void gram_kernel() {
    int side = blockIdx.z;
    int b    = blockIdx.y;
    int k0   = blockIdx.x * 512;
    const float* U = (side ? g_Ut : g_Us) + (size_t)b * NCH * PIX129;

    __shared__ __align__(8) float sm[NCH][514];
    int tid = threadIdx.x;
    for (int idx = tid; idx < NCH * 512; idx += 256) {
        int i = idx >> 9, kk = idx & 511;
        int k = k0 + kk;
        sm[i][kk] = (k < PIX129) ? U[(size_t)i * PIX129 + k] : 0.f;
    }
    __syncthreads();

    if (tid < 190) {
        int i = 0, t = tid;
        while (t >= NCH - i) { t -= NCH - i; i++; }
        int j = i + t;
        const u64* ri = (const u64*)&sm[i][0];
        const u64* rj = (const u64*)&sm[j][0];
        u64 acc2 = pack2(0.f, 0.f);
#pragma unroll 4
        for (int kk = 0; kk < 256; kk++) fma2(acc2, ri[kk], rj[kk]);
        float lo, hi;
        unpack2(lo, hi, acc2);
        atomicAdd(&g_R[side][b][tid], (double)(lo + hi));
    }
}

// ---------------------------------------------------------------------------
__global__ void finalize_kernel(float* __restrict__ out) {
    int tid = threadIdx.x;
    __shared__ double sE[2][NCH];
    __shared__ double sG[2][361];
    __shared__ double sS[2][361];
    __shared__ double sN[2][NCH];
    __shared__ double red[512];

    if (tid < 2 * NCH) {
        int side = tid / NCH, i = tid % NCH;
        double e = 0.0;
        for (int b = 0; b < NB; b++) {
            double d = g_d[side][b * NCH + i];
            e += g_Wz[side][b * NCH + i] / d - log(d);
        }
        sE[side][i] = e;
    }
    if (tid < 361) {
        int i = tid / NCH, j = tid % NCH;
        int mi = min(i, j), mj = max(i, j);
        int p = mi * NCH - mi * (mi - 1) / 2 + (mj - mi);
        for (int side = 0; side < 2; side++) {
            double g = 0.0;
            for (int b = 0; b < NB; b++)
                g += g_R[side][b][p] /
                     (g_d[side][b * NCH + i] * g_d[side][b * NCH + j]);
            sG[side][tid] = g;
        }
    }
    __syncthreads();
    if (tid < 361) {
        int i = tid / NCH, j = tid % NCH;
        int mx = max(i, j);
        sS[0][tid] = (sE[0][mx] - sG[0][tid]) / (double)NB;
        sS[1][tid] = (sE[1][mx] - sG[1][tid]) / (double)NB;
    }
    __syncthreads();
    if (tid < 2 * NCH) {
        int side = tid / NCH, i = tid % NCH;
        double s = 0.0;
        for (int j = 0; j < NCH; j++) {
            double v = sS[side][i * NCH + j];
            s += v * v;
        }
        double n = sqrt(s);
        sN[side][i] = (n > 1e-12) ? n : 1e-12;
    }
    __syncthreads();
    double v = 0.0;
    if (tid < 361) {
        int i = tid / NCH;
        double dd = sS[0][tid] / sN[0][i] - sS[1][tid] / sN[1][i];
        v = dd * dd;
    }
    red[tid] = v;
    __syncthreads();
    for (int o = 256; o; o >>= 1) {
        if (tid < o) red[tid] += red[tid + o];
        __syncthreads();
    }
    if (tid == 0) {
        out[0] = (float)(g_pi / 25958400.0);
        out[1] = (float)red[0];
    }
}

// ---------------------------------------------------------------------------
extern "C" void kernel_launch(void* const* d_in, const int* in_sizes, int n_in,
                              void* d_out, int out_size) {
    const float *ptr[6] = {nullptr, nullptr, nullptr, nullptr, nullptr, nullptr};
    const int want[6] = {1115136, 25958400, 642200, 2529912, 98304, 768};

    for (int i = 0; i < n_in; i++) {
        long long s = in_sizes[i];
        for (int k = 0; k < 6; k++) {
            if (s == (long long)want[k] || s == 4LL * want[k]) {
                if (!ptr[k]) ptr[k] = (const float*)d_in[i];
            }
        }
    }
    if (n_in >= 6) {
        for (int k = 0; k < 6; k++)
            if (!ptr[k]) ptr[k] = (const float*)d_in[k];
    }

    const float* s_out   = ptr[0];
    const float* t_out   = ptr[1];
    const float* t_logit = ptr[2];
    const float* s_logit = ptr[3];
    const float* conv_w  = ptr[4];
    const float* conv_b  = ptr[5];

    // Main (captured default) stream: zero -> fork.
    zero_kernel<<<15, 256>>>();
    cudaEventRecord(g_e1, 0);
    cudaStreamWaitEvent(g_s2, g_e1, 0);

    // Chain 1 (default stream): conv + pi path.
    transpose_w_kernel<<<(CIN * COUT + 255) / 256, 256>>>(conv_w);
    gemm_kernel<<<dim3(9, 6, NB), 256>>>(s_out, conv_b);
    pi_partial_kernel<<<dim3(67, NB, NSLICE), dim3(32, 8)>>>(t_out);
    pi_final_kernel<<<dim3((PIX65 + 255) / 256, NB), 256>>>();

    // Chain 2 (side stream): lo path.
    tprep_kernel<<<dim3((PIX129 + 255) / 256, NB * NCH), 256, 0, g_s2>>>(t_logit);
    sprep_kernel<<<dim3((PIX129 + 255) / 256, NB * NCH), 256, 0, g_s2>>>(s_logit);
    gram_kernel<<<dim3((PIX129 + 511) / 512, NB, 2), 256, 0, g_s2>>>();

    // Join and finalize.
    cudaEventRecord(g_e2, g_s2);
    cudaStreamWaitEvent(0, g_e2, 0);
    finalize_kernel<<<1, 512>>>((float*)d_out);
}

// round 8
// speedup vs baseline: 1.4589x; 1.1386x over previous
#include <cuda_runtime.h>
#include <cuda_bf16.h>
#include <cstdint>
#include <math.h>

// ---------------------------------------------------------------------------
#define PIX33 1089
#define PITCH33 1092
#define PIXPAD 1152            // 18 tiles of 64
#define PIX65 4225
#define PIX129 16641
#define CIN 128
#define COUT 768
#define NB 8
#define NCH 19
#define NSLICE 4

typedef unsigned long long u64;

__device__ __forceinline__ u64 pack2(float lo, float hi) {
    u64 r; asm("mov.b64 %0, {%1, %2};" : "=l"(r) : "f"(lo), "f"(hi)); return r;
}
__device__ __forceinline__ void unpack2(float& lo, float& hi, u64 v) {
    asm("mov.b64 {%0, %1}, %2;" : "=f"(lo), "=f"(hi) : "l"(v));
}
__device__ __forceinline__ void fma2(u64& d, u64 a, u64 b) {
    asm("fma.rn.f32x2 %0, %1, %2, %3;" : "=l"(d) : "l"(a), "l"(b), "l"(d));
}
__device__ __forceinline__ void mma16816(float* c, uint32_t a0, uint32_t a1,
                                         uint32_t a2, uint32_t a3,
                                         uint32_t b0, uint32_t b1) {
    asm volatile(
        "mma.sync.aligned.m16n8k16.row.col.f32.bf16.bf16.f32 "
        "{%0,%1,%2,%3}, {%4,%5,%6,%7}, {%8,%9}, {%0,%1,%2,%3};"
        : "+f"(c[0]), "+f"(c[1]), "+f"(c[2]), "+f"(c[3])
        : "r"(a0), "r"(a1), "r"(a2), "r"(a3), "r"(b0), "r"(b1));
}

__device__ __align__(16) __nv_bfloat16 g_Wbf[COUT * CIN];        // [o][k]
__device__ __align__(16) __nv_bfloat16 g_Sbf[NB * PIXPAD * CIN]; // [b][pix][k]
__device__ __align__(16) float g_y33[NB * COUT * PITCH33];
__device__ __align__(16) float g_Ut[NB * NCH * PIX129];
__device__ __align__(16) float g_Us[NB * NCH * PIX129];
__device__ __align__(16) float g_part[NSLICE][NB][4][PIX65];
__device__ double g_pi;
__device__ double g_d[2][NB * NCH];
__device__ double g_Wz[2][NB * NCH];
__device__ double g_R[2][NB][190];

static cudaStream_t g_s2;
static cudaEvent_t g_e1, g_e2;
namespace {
struct StreamInit {
    StreamInit() {
        cudaStreamCreateWithFlags(&g_s2, cudaStreamNonBlocking);
        cudaEventCreateWithFlags(&g_e1, cudaEventDisableTiming);
        cudaEventCreateWithFlags(&g_e2, cudaEventDisableTiming);
    }
};
static StreamInit g_si;
}

// ---------------------------------------------------------------------------
__global__ void zero_kernel() {
    int t = blockIdx.x * blockDim.x + threadIdx.x;
    if (t == 0) g_pi = 0.0;
    if (t < NB * NCH) {
        g_d[0][t] = 0.0; g_d[1][t] = 0.0;
        g_Wz[0][t] = 0.0; g_Wz[1][t] = 0.0;
    }
    if (t < 2 * NB * 190) ((double*)g_R)[t] = 0.0;
}

// conv_w fp32 [768][128] -> bf16, same layout (K contiguous).
__global__ void wbf_kernel(const float* __restrict__ conv_w) {
    int idx = blockIdx.x * blockDim.x + threadIdx.x;
    if (idx < COUT * CIN)
        g_Wbf[idx] = __float2bfloat16(conv_w[idx]);
}

// s_out fp32 [b][c][pix] -> bf16 transposed [b][pix][c] (zero-padded pix).
__global__ __launch_bounds__(256) void sbf_kernel(const float* __restrict__ s_out) {
    __shared__ float t[64][129];
    int b = blockIdx.y, p0 = blockIdx.x * 64;
    int tid = threadIdx.x;
    int px = tid & 63, c4 = tid >> 6;
    const float* base = s_out + (size_t)b * CIN * PIX33;
    for (int c0 = 0; c0 < CIN; c0 += 4) {
        int c = c0 + c4;
        int pix = p0 + px;
        t[px][c] = (pix < PIX33) ? base[(size_t)c * PIX33 + pix] : 0.f;
    }
    __syncthreads();
    int cp = (tid & 63) * 2, row = tid >> 6;
    for (int r0 = 0; r0 < 64; r0 += 4) {
        int r = r0 + row;
        __nv_bfloat162 v;
        v.x = __float2bfloat16(t[r][cp]);
        v.y = __float2bfloat16(t[r][cp + 1]);
        *(__nv_bfloat162*)&g_Sbf[((size_t)b * PIXPAD + p0 + r) * CIN + cp] = v;
    }
}

// ---------------------------------------------------------------------------
// Tensor-core GEMM: y33[b][o][pix] = sum_k Wbf[o][k]*Sbf[b][pix][k] + bias[o]
// Tile 64(o) x 64(pix), K=128 resident. 8 warps: 4 m-tiles x 2 n-halves.
// ---------------------------------------------------------------------------
__global__ __launch_bounds__(256) void gemm_mma_kernel(const float* __restrict__ bias) {
    int b    = blockIdx.z;
    int p0   = blockIdx.x * 64;
    int o0   = blockIdx.y * 64;

    __shared__ __align__(16) __nv_bfloat16 Asm[64][136];  // o x k
    __shared__ __align__(16) __nv_bfloat16 Bsm[64][136];  // pix x k

    int tid = threadIdx.x;
    // Load tiles: 64 rows x 256B each = 1024 16B chunks per tile; 4 per thread.
#pragma unroll
    for (int i = 0; i < 4; i++) {
        int id = tid + i * 256;
        int r = id >> 4, c16 = id & 15;
        *(uint4*)&Asm[r][c16 * 8] =
            *(const uint4*)&g_Wbf[(size_t)(o0 + r) * CIN + c16 * 8];
        *(uint4*)&Bsm[r][c16 * 8] =
            *(const uint4*)&g_Sbf[((size_t)b * PIXPAD + p0 + r) * CIN + c16 * 8];
    }
    __syncthreads();

    int w = tid >> 5, lane = tid & 31;
    int mo = (w & 3) * 16;           // m-tile base (o rows within tile)
    int n0 = (w >> 2) * 32;          // n-half base (pix cols within tile)
    int lr = lane >> 2;              // 0..7
    int lc = (lane & 3) * 2;         // 0,2,4,6

    float acc[4][4];
#pragma unroll
    for (int t = 0; t < 4; t++)
#pragma unroll
        for (int j = 0; j < 4; j++) acc[t][j] = 0.f;

#pragma unroll
    for (int ks = 0; ks < 8; ks++) {
        int kb = ks * 16;
        uint32_t a0 = *(uint32_t*)&Asm[mo + lr][kb + lc];
        uint32_t a1 = *(uint32_t*)&Asm[mo + lr + 8][kb + lc];
        uint32_t a2 = *(uint32_t*)&Asm[mo + lr][kb + lc + 8];
        uint32_t a3 = *(uint32_t*)&Asm[mo + lr + 8][kb + lc + 8];
#pragma unroll
        for (int t = 0; t < 4; t++) {
            int nr = n0 + t * 8 + lr;
            uint32_t b0 = *(uint32_t*)&Bsm[nr][kb + lc];
            uint32_t b1 = *(uint32_t*)&Bsm[nr][kb + lc + 8];
            mma16816(acc[t], a0, a1, a2, a3, b0, b1);
        }
    }

    // Epilogue: c0,c1 -> (row lr, pix lc,lc+1); c2,c3 -> (row lr+8).
    int o_  = o0 + mo + lr;
    float bb0 = bias[o_];
    float bb1 = bias[o_ + 8];
    float* row0 = g_y33 + ((size_t)b * COUT + o_) * PITCH33;
    float* row1 = row0 + (size_t)8 * PITCH33;
#pragma unroll
    for (int t = 0; t < 4; t++) {
        int pix = p0 + n0 + t * 8 + lc;
        if (pix + 1 < PIX33) {
            *(float2*)&row0[pix] = make_float2(acc[t][0] + bb0, acc[t][1] + bb0);
            *(float2*)&row1[pix] = make_float2(acc[t][2] + bb1, acc[t][3] + bb1);
        } else {
            if (pix < PIX33)     { row0[pix]     = acc[t][0] + bb0; row1[pix]     = acc[t][2] + bb1; }
            if (pix + 1 < PIX33) { row0[pix + 1] = acc[t][1] + bb0; row1[pix + 1] = acc[t][3] + bb1; }
        }
    }
}

// ---------------------------------------------------------------------------
// pi partial: 64 pixels x 192 channels per block; 2 pixels per thread.
// ---------------------------------------------------------------------------
__global__ __launch_bounds__(256) void pi_partial_kernel(const float* __restrict__ t_out) {
    int b     = blockIdx.y;
    int slice = blockIdx.z;
    int tx = threadIdx.x, ty = threadIdx.y;
    int pA = blockIdx.x * 64 + tx;
    int pB = pA + 32;
    bool vA = (pA < PIX65), vB = (pB < PIX65);
    int ppA = vA ? pA : 0;
    int ppB = vB ? pB : 0;

    int yA = ppA / 65, xA = ppA - yA * 65;
    int y0A = yA >> 1, x0A = xA >> 1;
    int y1A = min(y0A + 1, 32), x1A = min(x0A + 1, 32);
    float wyA = (yA & 1) * 0.5f, wxA = (xA & 1) * 0.5f;
    float a00 = (1.f - wyA) * (1.f - wxA), a01 = (1.f - wyA) * wxA;
    float a10 = wyA * (1.f - wxA),         a11 = wyA * wxA;
    int iA00 = y0A * 33 + x0A, iA01 = y0A * 33 + x1A;
    int iA10 = y1A * 33 + x0A, iA11 = y1A * 33 + x1A;

    int yB = ppB / 65, xB = ppB - yB * 65;
    int y0B = yB >> 1, x0B = xB >> 1;
    int y1B = min(y0B + 1, 32), x1B = min(x0B + 1, 32);
    float wyB = (yB & 1) * 0.5f, wxB = (xB & 1) * 0.5f;
    float b00 = (1.f - wyB) * (1.f - wxB), b01 = (1.f - wyB) * wxB;
    float b10 = wyB * (1.f - wxB),         b11 = wyB * wxB;
    int iB00 = y0B * 33 + x0B, iB01 = y0B * 33 + x1B;
    int iB10 = y1B * 33 + x0B, iB11 = y1B * 33 + x1B;

    const float* tpA = t_out + (size_t)b * COUT * PIX65
                     + (size_t)(slice * 192 + ty) * PIX65 + ppA;
    const float* tpB = t_out + (size_t)b * COUT * PIX65
                     + (size_t)(slice * 192 + ty) * PIX65 + ppB;
    const float* yp  = g_y33 + ((size_t)b * COUT + slice * 192 + ty) * PITCH33;

    float S1a = 0.f, S2a = 0.f, S3a = 0.f, Ssa = 0.f;
    float S1b = 0.f, S2b = 0.f, S3b = 0.f, Ssb = 0.f;

    for (int k = 0; k < 6; k++) {
#pragma unroll
        for (int u = 0; u < 4; u++) {
            const float* Y  = yp + (size_t)(u * 8) * PITCH33;
            float ztA = tpA[(size_t)(u * 8) * PIX65];
            float ztB = tpB[(size_t)(u * 8) * PIX65];
            float zsA = a00 * Y[iA00] + a01 * Y[iA01]
                      + a10 * Y[iA10] + a11 * Y[iA11];
            float zsB = b00 * Y[iB00] + b01 * Y[iB01]
                      + b10 * Y[iB10] + b11 * Y[iB11];
            float eA = __expf(ztA);
            float eB = __expf(ztB);
            S1a += eA;        S1b += eB;
            S2a += ztA * eA;  S2b += ztB * eB;
            S3a += zsA * eA;  S3b += zsB * eB;
            Ssa += __expf(zsA);
            Ssb += __expf(zsB);
        }
        tpA += (size_t)32 * PIX65;
        tpB += (size_t)32 * PIX65;
        yp  += (size_t)32 * PITCH33;
    }

    __shared__ float r1[8][64], r2[8][64], r3[8][64], rs[8][64];
    r1[ty][tx] = S1a; r1[ty][tx + 32] = S1b;
    r2[ty][tx] = S2a; r2[ty][tx + 32] = S2b;
    r3[ty][tx] = S3a; r3[ty][tx + 32] = S3b;
    rs[ty][tx] = Ssa; rs[ty][tx + 32] = Ssb;
    __syncthreads();

    if (ty < 2) {
        int col = ty * 32 + tx;
        int p   = blockIdx.x * 64 + col;
        if (p < PIX65) {
            float S1 = 0.f, S2 = 0.f, S3 = 0.f, Ss = 0.f;
#pragma unroll
            for (int u = 0; u < 8; u++) {
                S1 += r1[u][col]; S2 += r2[u][col];
                S3 += r3[u][col]; Ss += rs[u][col];
            }
            g_part[slice][b][0][p] = S1;
            g_part[slice][b][1][p] = S2;
            g_part[slice][b][2][p] = S3;
            g_part[slice][b][3][p] = Ss;
        }
    }
}

__global__ void pi_final_kernel() {
    int b = blockIdx.y;
    int p = blockIdx.x * 256 + threadIdx.x;
    float v = 0.f;
    if (p < PIX65) {
        float S1 = 0.f, S2 = 0.f, S3 = 0.f, Ss = 0.f;
#pragma unroll
        for (int s = 0; s < NSLICE; s++) {
            S1 += g_part[s][b][0][p];
            S2 += g_part[s][b][1][p];
            S3 += g_part[s][b][2][p];
            Ss += g_part[s][b][3][p];
        }
        float inv = 1.f / S1;
        v = S2 * inv - logf(S1) - S3 * inv + logf(Ss);
    }
    __shared__ float red[256];
    int tid = threadIdx.x;
    red[tid] = v;
    __syncthreads();
    for (int o = 128; o; o >>= 1) {
        if (tid < o) red[tid] += red[tid + o];
        __syncthreads();
    }
    if (tid == 0) atomicAdd(&g_pi, (double)red[0]);
}

// ---------------------------------------------------------------------------
__device__ __forceinline__ void prep_reduce_store(float dloc, float wloc,
                                                  int side, int row) {
    __shared__ float rd[256], rw[256];
    int tid = threadIdx.x;
    rd[tid] = dloc; rw[tid] = wloc;
    __syncthreads();
    for (int o = 128; o; o >>= 1) {
        if (tid < o) { rd[tid] += rd[tid + o]; rw[tid] += rw[tid + o]; }
        __syncthreads();
    }
    if (tid == 0) {
        atomicAdd(&g_d[side][row], (double)rd[0]);
        atomicAdd(&g_Wz[side][row], (double)rw[0]);
    }
}

__global__ void tprep_kernel(const float* __restrict__ t_logit) {
    int row = blockIdx.y;
    int k = blockIdx.x * 256 + threadIdx.x;
    float dloc = 0.f, wloc = 0.f;
    if (k < PIX129) {
        int y = k / 129, x = k - y * 129;
        int y0 = y >> 1, x0 = x >> 1;
        int y1 = min(y0 + 1, 64), x1 = min(x0 + 1, 64);
        float wy = (y & 1) * 0.5f, wx = (x & 1) * 0.5f;
        const float* src = t_logit + (size_t)row * PIX65;
        float top = (1.f - wx) * src[y0 * 65 + x0] + wx * src[y0 * 65 + x1];
        float bot = (1.f - wx) * src[y1 * 65 + x0] + wx * src[y1 * 65 + x1];
        float z = (1.f - wy) * top + wy * bot;
        float u = __expf(z);
        g_Ut[(size_t)row * PIX129 + k] = u;
        dloc = u; wloc = u * z;
    }
    prep_reduce_store(dloc, wloc, 1, row);
}

__global__ void sprep_kernel(const float* __restrict__ s_logit) {
    int row = blockIdx.y;
    int k = blockIdx.x * 256 + threadIdx.x;
    float dloc = 0.f, wloc = 0.f;
    if (k < PIX129) {
        float z = s_logit[(size_t)row * PIX129 + k];
        float u = __expf(z);
        g_Us[(size_t)row * PIX129 + k] = u;
        dloc = u; wloc = u * z;
    }
    prep_reduce_store(dloc, wloc, 0, row);
}

// ---------------------------------------------------------------------------
__global__ void gram_kernel() {
    int side = blockIdx.z;
    int b    = blockIdx.y;
    int k0   = blockIdx.x * 512;
    const float* U = (side ? g_Ut : g_Us) + (size_t)b * NCH * PIX129;

    __shared__ __align__(8) float sm[NCH][514];
    int tid = threadIdx.x;
    for (int idx = tid; idx < NCH * 512; idx += 256) {
        int i = idx >> 9, kk = idx & 511;
        int k = k0 + kk;
        sm[i][kk] = (k < PIX129) ? U[(size_t)i * PIX129 + k] : 0.f;
    }
    __syncthreads();

    if (tid < 190) {
        int i = 0, t = tid;
        while (t >= NCH - i) { t -= NCH - i; i++; }
        int j = i + t;
        const u64* ri = (const u64*)&sm[i][0];
        const u64* rj = (const u64*)&sm[j][0];
        u64 acc2 = pack2(0.f, 0.f);
#pragma unroll 4
        for (int kk = 0; kk < 256; kk++) fma2(acc2, ri[kk], rj[kk]);
        float lo, hi;
        unpack2(lo, hi, acc2);
        atomicAdd(&g_R[side][b][tid], (double)(lo + hi));
    }
}

// ---------------------------------------------------------------------------
__global__ void finalize_kernel(float* __restrict__ out) {
    int tid = threadIdx.x;
    __shared__ double sE[2][NCH];
    __shared__ double sG[2][361];
    __shared__ double sS[2][361];
    __shared__ double sN[2][NCH];
    __shared__ double red[512];

    if (tid < 2 * NCH) {
        int side = tid / NCH, i = tid % NCH;
        double e = 0.0;
        for (int b = 0; b < NB; b++) {
            double d = g_d[side][b * NCH + i];
            e += g_Wz[side][b * NCH + i] / d - log(d);
        }
        sE[side][i] = e;
    }
    if (tid < 361) {
        int i = tid / NCH, j = tid % NCH;
        int mi = min(i, j), mj = max(i, j);
        int p = mi * NCH - mi * (mi - 1) / 2 + (mj - mi);
        for (int side = 0; side < 2; side++) {
            double g = 0.0;
            for (int b = 0; b < NB; b++)
                g += g_R[side][b][p] /
                     (g_d[side][b * NCH + i] * g_d[side][b * NCH + j]);
            sG[side][tid] = g;
        }
    }
    __syncthreads();
    if (tid < 361) {
        int i = tid / NCH, j = tid % NCH;
        int mx = max(i, j);
        sS[0][tid] = (sE[0][mx] - sG[0][tid]) / (double)NB;
        sS[1][tid] = (sE[1][mx] - sG[1][tid]) / (double)NB;
    }
    __syncthreads();
    if (tid < 2 * NCH) {
        int side = tid / NCH, i = tid % NCH;
        double s = 0.0;
        for (int j = 0; j < NCH; j++) {
            double v = sS[side][i * NCH + j];
            s += v * v;
        }
        double n = sqrt(s);
        sN[side][i] = (n > 1e-12) ? n : 1e-12;
    }
    __syncthreads();
    double v = 0.0;
    if (tid < 361) {
        int i = tid / NCH;
        double dd = sS[0][tid] / sN[0][i] - sS[1][tid] / sN[1][i];
        v = dd * dd;
    }
    red[tid] = v;
    __syncthreads();
    for (int o = 256; o; o >>= 1) {
        if (tid < o) red[tid] += red[tid + o];
        __syncthreads();
    }
    if (tid == 0) {
        out[0] = (float)(g_pi / 25958400.0);
        out[1] = (float)red[0];
    }
}

// ---------------------------------------------------------------------------
extern "C" void kernel_launch(void* const* d_in, const int* in_sizes, int n_in,
                              void* d_out, int out_size) {
    const float *ptr[6] = {nullptr, nullptr, nullptr, nullptr, nullptr, nullptr};
    const int want[6] = {1115136, 25958400, 642200, 2529912, 98304, 768};

    for (int i = 0; i < n_in; i++) {
        long long s = in_sizes[i];
        for (int k = 0; k < 6; k++) {
            if (s == (long long)want[k] || s == 4LL * want[k]) {
                if (!ptr[k]) ptr[k] = (const float*)d_in[i];
            }
        }
    }
    if (n_in >= 6) {
        for (int k = 0; k < 6; k++)
            if (!ptr[k]) ptr[k] = (const float*)d_in[k];
    }

    const float* s_out   = ptr[0];
    const float* t_out   = ptr[1];
    const float* t_logit = ptr[2];
    const float* s_logit = ptr[3];
    const float* conv_w  = ptr[4];
    const float* conv_b  = ptr[5];

    // Main stream: zero -> fork.
    zero_kernel<<<15, 256>>>();
    cudaEventRecord(g_e1, 0);
    cudaStreamWaitEvent(g_s2, g_e1, 0);

    // Chain 1 (default stream): bf16 prep + tensor GEMM + pi path.
    wbf_kernel<<<(COUT * CIN + 255) / 256, 256>>>(conv_w);
    sbf_kernel<<<dim3(18, NB), 256>>>(s_out);
    gemm_mma_kernel<<<dim3(18, 12, NB), 256>>>(conv_b);
    pi_partial_kernel<<<dim3(67, NB, NSLICE), dim3(32, 8)>>>(t_out);
    pi_final_kernel<<<dim3((PIX65 + 255) / 256, NB), 256>>>();

    // Chain 2 (side stream): lo path.
    tprep_kernel<<<dim3((PIX129 + 255) / 256, NB * NCH), 256, 0, g_s2>>>(t_logit);
    sprep_kernel<<<dim3((PIX129 + 255) / 256, NB * NCH), 256, 0, g_s2>>>(s_logit);
    gram_kernel<<<dim3((PIX129 + 511) / 512, NB, 2), 256, 0, g_s2>>>();

    // Join and finalize.
    cudaEventRecord(g_e2, g_s2);
    cudaStreamWaitEvent(0, g_e2, 0);
    finalize_kernel<<<1, 512>>>((float*)d_out);
}